// round 1
// baseline (speedup 1.0000x reference)
#include <cuda_runtime.h>
#include <math.h>

// ---------------- problem constants (fixed shapes) ----------------
#define B_      2
#define N_      6
#define CAMS    (B_ * N_)          // 12
#define CAM_C   256
#define OUT_C   64
#define D_BINS  59
#define M_FEAT  (D_BINS + OUT_C)   // 123
#define FH      16
#define FW      44
#define HW      (FH * FW)          // 704
#define NX      128
#define NY      128
#define NCELL   (NX * NY)          // 16384 (NZ = 1)

// GEMM tiling
#define BM 128      // padded from 123
#define BN 64       // pixels per block
#define BK 32
#define NTHREADS 256

// scratch BEV accumulator, channel-contiguous: (B, cell, OUT_C)
__device__ float g_scratch[B_ * NCELL * OUT_C];   // 8 MB

// ---------------- zero scratch ----------------
__global__ void zero_scratch_kernel() {
    size_t i = (size_t)blockIdx.x * blockDim.x + threadIdx.x;
    float4 z = make_float4(0.f, 0.f, 0.f, 0.f);
    ((float4*)g_scratch)[i] = z;   // grid sized exactly to element count / 4
}

// ---------------- fused GEMM + softmax + scatter ----------------
__global__ __launch_bounds__(NTHREADS, 1)
void lss_fused_kernel(const float* __restrict__ x,
                      const float* __restrict__ rots,
                      const float* __restrict__ trans,
                      const float* __restrict__ intrins,
                      const float* __restrict__ depth_w,
                      const float* __restrict__ depth_b)
{
    // union'd shared memory:
    // phase 1 (GEMM): Ws[BK][BM+1] (16512B) + Xs[BK][BN+4] (8704B)  = 25216B
    // phase 2:        depthS[59][64] (15104B) + ctxS[64][64] (16384B) = 31488B
    __shared__ __align__(16) unsigned char smem_raw[(D_BINS * BN + BN * OUT_C) * 4];
    __shared__ float comb[9];
    __shared__ float tr[3];

    float (*Ws)[BM + 1]  = (float (*)[BM + 1]) smem_raw;
    float (*Xs)[BN + 4]  = (float (*)[BN + 4]) (smem_raw + BK * (BM + 1) * 4);

    const int cam = blockIdx.y;           // 0..11
    const int b   = cam / N_;
    const int p0  = blockIdx.x * BN;      // pixel tile start (hw index)
    const int tid = threadIdx.x;
    const int tm  = tid >> 4;             // 0..15 -> 8 rows of M each
    const int tn  = tid & 15;             // 0..15 -> 4 pixels each

    // --- geometry setup: comb = rots @ inv(K), trans copy (thread 0) ---
    if (tid == 0) {
        const float* R = rots    + cam * 9;
        const float* K = intrins + cam * 9;
        float a = K[0], bb = K[1], c = K[2];
        float d = K[3], e  = K[4], f = K[5];
        float g = K[6], h  = K[7], i = K[8];
        float A  = e * i - f * h;
        float Bv = -(d * i - f * g);
        float Cv = d * h - e * g;
        float det = a * A + bb * Bv + c * Cv;
        float id = 1.0f / det;
        float inv[9];
        inv[0] = A * id;             inv[1] = (c * h - bb * i) * id; inv[2] = (bb * f - c * e) * id;
        inv[3] = Bv * id;            inv[4] = (a * i - c * g) * id;  inv[5] = (c * d - a * f) * id;
        inv[6] = Cv * id;            inv[7] = (bb * g - a * h) * id; inv[8] = (a * e - bb * d) * id;
        #pragma unroll
        for (int r = 0; r < 3; r++)
            #pragma unroll
            for (int col = 0; col < 3; col++)
                comb[r * 3 + col] = R[r * 3 + 0] * inv[0 + col]
                                  + R[r * 3 + 1] * inv[3 + col]
                                  + R[r * 3 + 2] * inv[6 + col];
        tr[0] = trans[cam * 3 + 0];
        tr[1] = trans[cam * 3 + 1];
        tr[2] = trans[cam * 3 + 2];
    }

    // --- phase 1: feat = W @ x  (M=128 pad, N=64 pixels, K=256) ---
    float acc[8][4];
    #pragma unroll
    for (int i = 0; i < 8; i++)
        #pragma unroll
        for (int j = 0; j < 4; j++) acc[i][j] = 0.f;

    const float* xcam = x + (size_t)cam * CAM_C * HW;

    for (int kc = 0; kc < CAM_C; kc += BK) {
        // load W chunk transposed: Ws[kk][m] = W[m][kc+kk]
        #pragma unroll
        for (int idx = tid; idx < BM * BK; idx += NTHREADS) {
            int m  = idx >> 5;
            int kk = idx & 31;
            Ws[kk][m] = (m < M_FEAT) ? depth_w[m * CAM_C + kc + kk] : 0.f;
        }
        // load X chunk: Xs[kk][np] = x[c=kc+kk][p0+np]
        #pragma unroll
        for (int idx = tid; idx < BK * BN; idx += NTHREADS) {
            int kk = idx >> 6;
            int np = idx & 63;
            Xs[kk][np] = xcam[(size_t)(kc + kk) * HW + p0 + np];
        }
        __syncthreads();

        #pragma unroll 8
        for (int kk = 0; kk < BK; kk++) {
            float xv0 = Xs[kk][tn * 4 + 0];
            float xv1 = Xs[kk][tn * 4 + 1];
            float xv2 = Xs[kk][tn * 4 + 2];
            float xv3 = Xs[kk][tn * 4 + 3];
            #pragma unroll
            for (int i = 0; i < 8; i++) {
                float wv = Ws[kk][tm * 8 + i];
                acc[i][0] += wv * xv0;
                acc[i][1] += wv * xv1;
                acc[i][2] += wv * xv2;
                acc[i][3] += wv * xv3;
            }
        }
        __syncthreads();
    }

    // --- phase 2: stash feat (+bias) into depthS / ctxS ---
    float* depthS = (float*)smem_raw;                 // [59][64] row-major
    float* ctxS   = (float*)smem_raw + D_BINS * BN;   // [64 pix][64 c], rows 256B aligned

    #pragma unroll
    for (int i = 0; i < 8; i++) {
        int m = tm * 8 + i;
        if (m < M_FEAT) {
            float bias = depth_b[m];
            #pragma unroll
            for (int j = 0; j < 4; j++) {
                int pix = tn * 4 + j;
                float v = acc[i][j] + bias;
                if (m < D_BINS) depthS[m * BN + pix] = v;
                else            ctxS[pix * OUT_C + (m - D_BINS)] = v;
            }
        }
    }
    __syncthreads();

    // --- softmax over depth bins, one thread per pixel ---
    if (tid < BN) {
        int pix = tid;
        float mx = -1e30f;
        #pragma unroll 4
        for (int d = 0; d < D_BINS; d++) mx = fmaxf(mx, depthS[d * BN + pix]);
        float s = 0.f;
        #pragma unroll 4
        for (int d = 0; d < D_BINS; d++) {
            float e = __expf(depthS[d * BN + pix] - mx);
            depthS[d * BN + pix] = e;
            s += e;
        }
        float invs = 1.0f / s;
        #pragma unroll 4
        for (int d = 0; d < D_BINS; d++) depthS[d * BN + pix] *= invs;
    }
    __syncthreads();

    // --- scatter: 64 pixels x 59 depth bins -> BEV grid via red.v4 ---
    const float c00 = comb[0], c01 = comb[1], c02 = comb[2];
    const float c10 = comb[3], c11 = comb[4], c12 = comb[5];
    const float c20 = comb[6], c21 = comb[7], c22 = comb[8];
    const float t0 = tr[0], t1 = tr[1], t2 = tr[2];
    const float xstep = 703.0f / 43.0f;   // linspace(0, IMG_W-1, FW) step
    const float ystep = 255.0f / 15.0f;   // = 17

    for (int idx = tid; idx < BN * D_BINS; idx += NTHREADS) {
        int pix = idx / D_BINS;
        int d   = idx - pix * D_BINS;
        int hw  = p0 + pix;
        int h   = hw / FW;
        int w   = hw - h * FW;

        float ds  = 1.0f + (float)d;        // depth value
        float xim = (float)w * xstep;
        float yim = (float)h * ystep;
        float px = xim * ds, py = yim * ds, pz = ds;

        float gx = c00 * px + c01 * py + c02 * pz + t0;
        float gy = c10 * px + c11 * py + c12 * pz + t1;
        float gz = c20 * px + c21 * py + c22 * pz + t2;

        int cx = (int)floorf((gx + 51.2f) / 0.8f);
        int cy = (int)floorf((gy + 51.2f) / 0.8f);
        int cz = (int)floorf((gz + 10.0f) / 20.0f);

        if (cx >= 0 && cx < NX && cy >= 0 && cy < NY && cz == 0) {
            float dwgt = depthS[d * BN + pix];
            float* dst = g_scratch + ((size_t)b * NCELL + (size_t)cy * NX + cx) * OUT_C;
            const float4* cv = (const float4*)(ctxS + pix * OUT_C);
            #pragma unroll
            for (int c4 = 0; c4 < OUT_C / 4; c4++) {
                float4 v = cv[c4];
                asm volatile(
                    "red.global.add.v4.f32 [%0], {%1, %2, %3, %4};"
                    :: "l"(dst + c4 * 4),
                       "f"(v.x * dwgt), "f"(v.y * dwgt), "f"(v.z * dwgt), "f"(v.w * dwgt)
                    : "memory");
            }
        }
    }
}

// ---------------- transpose (B, cell, C) -> (B, C, cell) ----------------
__global__ void transpose_bev_kernel(float* __restrict__ out)
{
    __shared__ float tile[32][33];
    int bz    = blockIdx.z;                 // batch
    int c0    = blockIdx.y * 32;            // channel tile (2)
    int cell0 = blockIdx.x * 32;            // cell tile (512)
    int tx = threadIdx.x, ty = threadIdx.y; // 32 x 8

    #pragma unroll
    for (int i = ty; i < 32; i += 8)
        tile[i][tx] = g_scratch[((size_t)bz * NCELL + cell0 + i) * OUT_C + c0 + tx];
    __syncthreads();
    #pragma unroll
    for (int i = ty; i < 32; i += 8)
        out[((size_t)(bz * OUT_C + c0 + i)) * NCELL + cell0 + tx] = tile[tx][i];
}

// ---------------- launch ----------------
extern "C" void kernel_launch(void* const* d_in, const int* in_sizes, int n_in,
                              void* d_out, int out_size)
{
    const float* x       = (const float*)d_in[0];
    const float* rots    = (const float*)d_in[1];
    const float* trans   = (const float*)d_in[2];
    const float* intrins = (const float*)d_in[3];
    const float* depth_w = (const float*)d_in[4];
    const float* depth_b = (const float*)d_in[5];
    float* out = (float*)d_out;

    // zero scratch accumulator (exactly one float4 per thread)
    {
        size_t n4 = (size_t)B_ * NCELL * OUT_C / 4;   // 524288
        zero_scratch_kernel<<<(unsigned)(n4 / 256), 256>>>();
    }

    // fused GEMM + softmax + scatter: one block per (camera, 64-pixel tile)
    {
        dim3 grid(HW / BN, CAMS);   // (11, 12)
        lss_fused_kernel<<<grid, NTHREADS>>>(x, rots, trans, intrins, depth_w, depth_b);
    }

    // transpose scratch into output layout (B, OUT_C, NY, NX)
    {
        dim3 grid(NCELL / 32, OUT_C / 32, B_);   // (512, 2, 2)
        transpose_bev_kernel<<<grid, dim3(32, 8)>>>(out);
    }
    (void)in_sizes; (void)n_in; (void)out_size;
}